// round 11
// baseline (speedup 1.0000x reference)
#include <cuda_runtime.h>
#include <cuda_fp16.h>
#include <math_constants.h>
#include <cstdint>

#define BB   4
#define SS   4096
#define EMBD 512
#define HD   64
#define LDW  36   // word stride for 64-col fp16 tiles (144B)
#define NSPLIT 3  // key splits (exact: pure-sum softmax). tiles: 22,21,21

// Projected activations, fp16. Q pre-scaled by log2(e)/sqrt(HD).
__device__ __half   g_Qh[BB * SS * HD];
__device__ __half   g_Kh[BB * SS * HD];
// V transposed + key-pair packed: word [b][d][k2] = {V[2k2][d], V[2k2+1][d]}
__device__ uint32_t g_Vp[BB * HD * (SS / 2)];
// W pre-converted to fp16: [m][HD][EMBD]
__device__ __half   g_Wh[3 * HD * EMBD];
// Split-K partials (unnormalized)
__device__ float g_Op[NSPLIT * BB * SS * HD];
__device__ float g_Lp[NSPLIT * BB * SS];

__device__ __forceinline__ uint32_t pack_h2(float lo, float hi) {
    __half2 h = __floats2half2_rn(lo, hi);
    return *reinterpret_cast<uint32_t*>(&h);
}

__device__ __forceinline__ void mma_f16(float* d, const uint32_t* a,
                                        uint32_t b0, uint32_t b1) {
    asm volatile(
        "mma.sync.aligned.m16n8k16.row.col.f32.f16.f16.f32 "
        "{%0,%1,%2,%3}, {%4,%5,%6,%7}, {%8,%9}, {%0,%1,%2,%3};\n"
        : "+f"(d[0]), "+f"(d[1]), "+f"(d[2]), "+f"(d[3])
        : "r"(a[0]), "r"(a[1]), "r"(a[2]), "r"(a[3]), "r"(b0), "r"(b1));
}

__device__ __forceinline__ void ldsm_x4(uint32_t* r, uint32_t addr) {
    asm volatile("ldmatrix.sync.aligned.m8n8.x4.shared.b16 {%0,%1,%2,%3}, [%4];\n"
                 : "=r"(r[0]), "=r"(r[1]), "=r"(r[2]), "=r"(r[3]) : "r"(addr));
}

__device__ __forceinline__ uint32_t sm_u32(const void* p) {
    uint32_t a;
    asm("{ .reg .u64 t; cvta.to.shared.u64 t, %1; cvt.u32.u64 %0, t; }"
        : "=r"(a) : "l"(p));
    return a;
}

__device__ __forceinline__ void cp_async16(uint32_t dst, const void* src) {
    asm volatile("cp.async.cg.shared.global [%0], [%1], 16;\n"
                 :: "r"(dst), "l"(src) : "memory");
}

// ---------------------------------------------------------------------------
// W fp32 -> fp16 preconversion (once; 3 x 64 x 512).
// ---------------------------------------------------------------------------
__global__ __launch_bounds__(256) void wconv_kernel(
    const float* __restrict__ Wq, const float* __restrict__ Wk, const float* __restrict__ Wv)
{
    const int idx = blockIdx.x * 256 + threadIdx.x;   // 24576 float4s
    const int m = idx >> 13;                          // 8192 float4 per matrix
    const int e = idx & 8191;
    const float* __restrict__ W = (m == 0) ? Wq : (m == 1) ? Wk : Wv;
    float4 v = ((const float4*)W)[e];
    ((uint2*)g_Wh)[(size_t)m * 8192 + e] =
        make_uint2(pack_h2(v.x, v.y), pack_h2(v.z, v.w));
}

// ---------------------------------------------------------------------------
// Projection v2: cp.async pipelined. CTA = 128 thr (4 warps), 64 rows.
// smem words: stageX 2x4352 @0 (fp32, stride 68), tileW 2x2304 @8704 (fp16),
//             tileX 2304 @13312 (fp16). Total 15616 w = 62464 B -> 3 CTAs/SM.
// ---------------------------------------------------------------------------
#define PSTG 68
#define PTW_OFF 8704
#define PTX_OFF 13312
#define PROJ_SMEM_WORDS 15616

extern __shared__ uint32_t sm_dyn[];

__device__ __forceinline__ void proj_issue(uint32_t smem_base, const float* x,
                                           const __half* Wh, int row0, int kc0,
                                           int buf, int tid)
{
    const int rr = tid >> 4;
    const int fc = tid & 15;
    #pragma unroll
    for (int it = 0; it < 8; it++) {
        int r = it * 8 + rr;
        cp_async16(smem_base + (buf * 4352 + r * PSTG + fc * 4) * 4,
                   &x[(size_t)(row0 + r) * EMBD + kc0 + fc * 4]);
    }
    #pragma unroll
    for (int it = 0; it < 4; it++) {
        int idx = it * 128 + tid;
        int r = idx >> 3, c = idx & 7;
        cp_async16(smem_base + (PTW_OFF + buf * 2304 + r * LDW + c * 4) * 4,
                   &Wh[(size_t)r * EMBD + kc0 + c * 8]);
    }
}

__global__ __launch_bounds__(128) void proj_kernel(
    const float* __restrict__ q, const float* __restrict__ k, const float* __restrict__ v)
{
    const int m = blockIdx.y;
    const float* __restrict__ x = (m == 0) ? q : (m == 1) ? k : v;
    const __half* __restrict__ Wh = g_Wh + (size_t)m * HD * EMBD;

    const int row0 = blockIdx.x * 64;
    const int tid  = threadIdx.x;
    const int w    = tid >> 5;
    const int lane = tid & 31;
    const int g    = lane >> 2;
    const int t    = lane & 3;
    const int rr   = tid >> 4;
    const int fc   = tid & 15;

    const uint32_t smem_base = sm_u32(sm_dyn);

    float o[8][4];
    #pragma unroll
    for (int j = 0; j < 8; j++)
        #pragma unroll
        for (int e = 0; e < 4; e++) o[j][e] = 0.0f;

    proj_issue(smem_base, x, Wh, row0, 0, 0, tid);
    asm volatile("cp.async.commit_group;\n" ::: "memory");

    for (int n = 0; n < 8; n++) {
        const int buf = n & 1;
        asm volatile("cp.async.wait_group 0;\n" ::: "memory");
        __syncthreads();   // chunk n staged; all warps finished mma(n-1)

        if (n + 1 < 8) {
            proj_issue(smem_base, x, Wh, row0, (n + 1) * 64, buf ^ 1, tid);
            asm volatile("cp.async.commit_group;\n" ::: "memory");
        }

        // convert staged x (fp32) -> tileX (fp16)
        #pragma unroll
        for (int it = 0; it < 8; it++) {
            int r = it * 8 + rr;
            float4 xv = *(const float4*)&sm_dyn[(buf * 4352 + r * PSTG + fc * 4)];
            *(uint2*)&sm_dyn[PTX_OFF + r * LDW + fc * 2] =
                make_uint2(pack_h2(xv.x, xv.y), pack_h2(xv.z, xv.w));
        }
        __syncthreads();

        const uint32_t* sX  = sm_dyn + PTX_OFF;
        const uint32_t* sWm = sm_dyn + PTW_OFF + buf * 2304;
        #pragma unroll
        for (int kc = 0; kc < 4; kc++) {
            uint32_t af[4];
            const uint32_t* xr = &sX[(16 * w + g) * LDW + 8 * kc + t];
            af[0] = xr[0];
            af[1] = xr[8 * LDW];
            af[2] = xr[4];
            af[3] = xr[8 * LDW + 4];
            #pragma unroll
            for (int j = 0; j < 8; j++) {
                mma_f16(o[j], af,
                        sWm[(8 * j + g) * LDW + 8 * kc + t],
                        sWm[(8 * j + g) * LDW + 8 * kc + t + 4]);
            }
        }
    }

    const int rowg = row0 + 16 * w + g;
    if (m < 2) {
        const float sc = (m == 0) ? 0.125f * 1.4426950408889634f : 1.0f;
        __half* dst = (m == 0) ? g_Qh : g_Kh;
        #pragma unroll
        for (int j = 0; j < 8; j++) {
            int c = 8 * j + 2 * t;
            *(uint32_t*)&dst[(size_t)rowg * HD + c] = pack_h2(o[j][0] * sc, o[j][1] * sc);
            *(uint32_t*)&dst[(size_t)(rowg + 8) * HD + c] = pack_h2(o[j][2] * sc, o[j][3] * sc);
        }
    } else {
        const int b  = rowg >> 12;
        const int k2 = (rowg & (SS - 1)) >> 1;
        const uint32_t sel = (g & 1) ? 0x3276u : 0x5410u;
        #pragma unroll
        for (int j = 0; j < 8; j++) {
            int c = 8 * j + 2 * t;
            uint32_t w0 = pack_h2(o[j][0], o[j][1]);
            uint32_t w1 = pack_h2(o[j][2], o[j][3]);
            uint32_t p0 = __shfl_xor_sync(0xffffffffu, w0, 4);
            uint32_t p1 = __shfl_xor_sync(0xffffffffu, w1, 4);
            int d = c + (g & 1);
            size_t base = ((size_t)b * HD + d) * (SS / 2);
            g_Vp[base + k2]     = __byte_perm(w0, p0, sel);
            g_Vp[base + k2 + 4] = __byte_perm(w1, p1, sel);
        }
    }
}

// ---------------------------------------------------------------------------
// Flash attention v9: 128 q-rows/CTA, 4 warps of 32q x 64keys (4:1 mma:LDSM),
// register-resident P, split-K NSPLIT=3. grid (32, 4, 3) = 384 CTAs, 3/SM.
// smem words: K 2x2304 @0, V 2x2304 @4608 -> 9216 w = 36864 B.
// Q (128x64) staged through K-buf1 (rows 0-63) and V-buf1 (rows 64-127).
// ---------------------------------------------------------------------------
#define SV_OFF 4608
#define ATTN_SMEM_WORDS 9216

__device__ __forceinline__ void issue_tile(uint32_t smem_base, int b, int kt, int buf, int tid)
{
    const __half*   Ksrc = g_Kh + ((size_t)b * SS + (size_t)kt * 64) * HD;
    const uint32_t* Vsrc = g_Vp + (size_t)b * HD * (SS / 2) + kt * 32;
    #pragma unroll
    for (int i = 0; i < 4; i++) {
        int ch = i * 128 + tid;             // 512 16B chunks per tile
        int r = ch >> 3, c = ch & 7;
        cp_async16(smem_base + (buf * 2304 + r * LDW + c * 4) * 4,
                   Ksrc + (size_t)r * HD + c * 8);
        cp_async16(smem_base + (SV_OFF + buf * 2304 + r * LDW + c * 4) * 4,
                   Vsrc + (size_t)r * (SS / 2) + c * 4);
    }
}

__global__ __launch_bounds__(128, 3) void attn_kernel()
{
    const int b    = blockIdx.y;
    const int z    = blockIdx.z;
    const int q0   = blockIdx.x * 128;
    const int tid  = threadIdx.x;
    const int w    = tid >> 5;      // warp: rows q0 + w*32 .. +31
    const int lane = tid & 31;
    const int g    = lane >> 2;
    const int t    = lane & 3;

    const uint32_t smem_base = sm_u32(sm_dyn);

    const int kt0 = (z == 0) ? 0 : (21 * z + 1);    // 0, 22, 43
    const int nkt = (z == 0) ? 22 : 21;

    issue_tile(smem_base, b, kt0, 0, tid);
    asm volatile("cp.async.commit_group;\n" ::: "memory");

    // Stage Q (128x64 fp16): rows 0-63 -> K-buf1, rows 64-127 -> V-buf1
    const __half* Qb = g_Qh + ((size_t)b * SS + q0) * HD;
    #pragma unroll
    for (int it = 0; it < 8; it++) {
        int idx = it * 128 + tid;           // 1024 16B chunks
        int r = idx >> 3, c = idx & 7;
        int dst = (r < 64) ? (2304 + r * LDW + c * 4)
                           : (SV_OFF + 2304 + (r - 64) * LDW + c * 4);
        *(uint4*)&sm_dyn[dst] = *(const uint4*)&Qb[(size_t)r * HD + c * 8];
    }
    __syncthreads();

    // Q fragments: 2 x 16-row tiles per warp (live whole kernel)
    uint32_t qf[2][4][4];
    #pragma unroll
    for (int tt = 0; tt < 2; tt++) {
        int base = w * 32 + tt * 16;        // 16-row block never crosses the 64 boundary
        const uint32_t* qp = (base < 64)
            ? &sm_dyn[2304 + (base + g) * LDW]
            : &sm_dyn[SV_OFF + 2304 + (base - 64 + g) * LDW];
        #pragma unroll
        for (int kc = 0; kc < 4; kc++) {
            qf[tt][kc][0] = qp[8 * kc + t];
            qf[tt][kc][1] = qp[8 * LDW + 8 * kc + t];
            qf[tt][kc][2] = qp[8 * kc + t + 4];
            qf[tt][kc][3] = qp[8 * LDW + 8 * kc + t + 4];
        }
    }

    float o[2][8][4];
    #pragma unroll
    for (int tt = 0; tt < 2; tt++)
        #pragma unroll
        for (int dj = 0; dj < 8; dj++)
            #pragma unroll
            for (int e = 0; e < 4; e++) o[tt][dj][e] = 0.0f;
    float l0[2] = {0.0f, 0.0f}, l1[2] = {0.0f, 0.0f};

    const uint32_t koff = ((lane & 7) * LDW + 4 * (lane >> 3)) * 4;

    int buf = 0;

    for (int it = 0; it < nkt; it++) {
        __syncthreads();   // all warps done with buf^1 (and qf extraction on it=0)
        if (it + 1 < nkt) {
            issue_tile(smem_base, b, kt0 + it + 1, buf ^ 1, tid);
            asm volatile("cp.async.commit_group;\n" ::: "memory");
            asm volatile("cp.async.wait_group 1;\n" ::: "memory");
        } else {
            asm volatile("cp.async.wait_group 0;\n" ::: "memory");
        }
        __syncthreads();

        const uint32_t kbase = smem_base + (buf * 2304) * 4 + koff;
        const uint32_t vbase = smem_base + (SV_OFF + buf * 2304) * 4 + koff;

        // ---- S = Q K^T over all 64 keys; exp2 per 8-key chunk ----
        uint32_t pl[2][8], ph[2][8];
        __half2 la0[2] = {__float2half2_rn(0.0f), __float2half2_rn(0.0f)};
        __half2 la1[2] = {__float2half2_rn(0.0f), __float2half2_rn(0.0f)};

        #pragma unroll
        for (int j = 0; j < 8; j++) {
            uint32_t kf[8];
            ldsm_x4(kf,     kbase + j * (8 * LDW * 4));
            ldsm_x4(kf + 4, kbase + j * (8 * LDW * 4) + 64);
            #pragma unroll
            for (int tt = 0; tt < 2; tt++) {
                float s[4] = {0.0f, 0.0f, 0.0f, 0.0f};
                mma_f16(s, qf[tt][0], kf[0], kf[1]);
                mma_f16(s, qf[tt][1], kf[2], kf[3]);
                mma_f16(s, qf[tt][2], kf[4], kf[5]);
                mma_f16(s, qf[tt][3], kf[6], kf[7]);
                __half2 e0 = h2exp2(__floats2half2_rn(s[0], s[1]));  // row w32+tt16+g
                __half2 e1 = h2exp2(__floats2half2_rn(s[2], s[3]));  // row +8
                la0[tt] = __hadd2(la0[tt], e0);
                la1[tt] = __hadd2(la1[tt], e1);
                pl[tt][j] = *reinterpret_cast<uint32_t*>(&e0);
                ph[tt][j] = *reinterpret_cast<uint32_t*>(&e1);
            }
        }
        #pragma unroll
        for (int tt = 0; tt < 2; tt++) {
            float2 f0 = __half22float2(la0[tt]); l0[tt] += f0.x + f0.y;
            float2 f1 = __half22float2(la1[tt]); l1[tt] += f1.x + f1.y;
        }

        // ---- O += P V : 64 keys = 4 A-chunks; V frags shared across tt ----
        #pragma unroll
        for (int dj = 0; dj < 8; dj++) {
            uint32_t vf[8];
            ldsm_x4(vf,     vbase + dj * (8 * LDW * 4));
            ldsm_x4(vf + 4, vbase + dj * (8 * LDW * 4) + 64);
            #pragma unroll
            for (int tt = 0; tt < 2; tt++) {
                uint32_t a0[4] = { pl[tt][0], ph[tt][0], pl[tt][1], ph[tt][1] };
                uint32_t a1[4] = { pl[tt][2], ph[tt][2], pl[tt][3], ph[tt][3] };
                uint32_t a2[4] = { pl[tt][4], ph[tt][4], pl[tt][5], ph[tt][5] };
                uint32_t a3[4] = { pl[tt][6], ph[tt][6], pl[tt][7], ph[tt][7] };
                mma_f16(o[tt][dj], a0, vf[0], vf[1]);
                mma_f16(o[tt][dj], a1, vf[2], vf[3]);
                mma_f16(o[tt][dj], a2, vf[4], vf[5]);
                mma_f16(o[tt][dj], a3, vf[6], vf[7]);
            }
        }
        buf ^= 1;
    }

    // ---- Reduce l over the 4 t-lanes; write unnormalized partials ----
    float* __restrict__ Ob = g_Op + (((size_t)z * BB + b) * SS + q0) * HD;
    float* __restrict__ Lb = g_Lp + ((size_t)z * BB + b) * SS + q0;
    #pragma unroll
    for (int tt = 0; tt < 2; tt++) {
        l0[tt] += __shfl_xor_sync(0xffffffffu, l0[tt], 1);
        l0[tt] += __shfl_xor_sync(0xffffffffu, l0[tt], 2);
        l1[tt] += __shfl_xor_sync(0xffffffffu, l1[tt], 1);
        l1[tt] += __shfl_xor_sync(0xffffffffu, l1[tt], 2);
        int r0 = w * 32 + tt * 16 + g;
        if (t == 0) {
            Lb[r0]     = l0[tt];
            Lb[r0 + 8] = l1[tt];
        }
        #pragma unroll
        for (int dj = 0; dj < 8; dj++) {
            int c = 8 * dj + 2 * t;
            *(float2*)&Ob[(size_t)r0 * HD + c] =
                make_float2(o[tt][dj][0], o[tt][dj][1]);
            *(float2*)&Ob[(size_t)(r0 + 8) * HD + c] =
                make_float2(o[tt][dj][2], o[tt][dj][3]);
        }
    }
}

// ---------------------------------------------------------------------------
// Merge: out = sum_z O_z / sum_z l_z.  One thread per float4.
// ---------------------------------------------------------------------------
__global__ __launch_bounds__(256) void merge_kernel(float* __restrict__ out)
{
    const int idx = blockIdx.x * 256 + threadIdx.x;      // over BB*SS*HD/4
    const int row = idx >> 4;                             // 16 float4 per row
    float l = g_Lp[row] + g_Lp[BB * SS + row] + g_Lp[2 * BB * SS + row];
    float inv = 1.0f / l;
    const float4 a = *(const float4*)&g_Op[(size_t)idx * 4];
    const float4 c = *(const float4*)&g_Op[(size_t)BB * SS * HD + (size_t)idx * 4];
    const float4 d = *(const float4*)&g_Op[2 * (size_t)BB * SS * HD + (size_t)idx * 4];
    ((float4*)out)[idx] = make_float4((a.x + c.x + d.x) * inv, (a.y + c.y + d.y) * inv,
                                      (a.z + c.z + d.z) * inv, (a.w + c.w + d.w) * inv);
}

// ---------------------------------------------------------------------------
extern "C" void kernel_launch(void* const* d_in, const int* in_sizes, int n_in,
                              void* d_out, int out_size)
{
    const float* q  = (const float*)d_in[0];
    const float* k  = (const float*)d_in[1];
    const float* v  = (const float*)d_in[2];
    const float* Wq = (const float*)d_in[3];
    const float* Wk = (const float*)d_in[4];
    const float* Wv = (const float*)d_in[5];
    float* out = (float*)d_out;

    const int smem_proj = PROJ_SMEM_WORDS * (int)sizeof(uint32_t);   // 62464 B
    const int smem_attn = ATTN_SMEM_WORDS * (int)sizeof(uint32_t);   // 36864 B
    cudaFuncSetAttribute(proj_kernel, cudaFuncAttributeMaxDynamicSharedMemorySize, smem_proj);
    cudaFuncSetAttribute(attn_kernel, cudaFuncAttributeMaxDynamicSharedMemorySize, smem_attn);

    wconv_kernel<<<96, 256>>>(Wq, Wk, Wv);
    proj_kernel<<<dim3((BB * SS) / 64, 3), 128, smem_proj>>>(q, k, v);
    attn_kernel<<<dim3(SS / 128, BB, NSPLIT), 128, smem_attn>>>();
    merge_kernel<<<(BB * SS * HD / 4) / 256, 256>>>(out);
}

// round 13
// speedup vs baseline: 1.0114x; 1.0114x over previous
#include <cuda_runtime.h>
#include <cuda_fp16.h>
#include <math_constants.h>
#include <cstdint>

#define BB   4
#define SS   4096
#define EMBD 512
#define HD   64
#define LDW  36   // word stride for 64-col fp16 tiles: 32 half2-words + 4 pad (144B)
#define NSPLIT 3  // key splits (exact: pure-sum softmax). tiles: 22,21,21

// Projected activations, fp16. Q pre-scaled by log2(e)/sqrt(HD).
__device__ __half   g_Qh[BB * SS * HD];
__device__ __half   g_Kh[BB * SS * HD];
// V transposed + key-pair packed: word [b][d][k2] = {V[2k2][d], V[2k2+1][d]}
__device__ uint32_t g_Vp[BB * HD * (SS / 2)];
// Split-K partials (unnormalized)
__device__ float g_Op[NSPLIT * BB * SS * HD];
__device__ float g_Lp[NSPLIT * BB * SS];

__device__ __forceinline__ uint32_t pack_h2(float lo, float hi) {
    __half2 h = __floats2half2_rn(lo, hi);
    return *reinterpret_cast<uint32_t*>(&h);
}

__device__ __forceinline__ void mma_f16(float* d, const uint32_t* a,
                                        uint32_t b0, uint32_t b1) {
    asm volatile(
        "mma.sync.aligned.m16n8k16.row.col.f32.f16.f16.f32 "
        "{%0,%1,%2,%3}, {%4,%5,%6,%7}, {%8,%9}, {%0,%1,%2,%3};\n"
        : "+f"(d[0]), "+f"(d[1]), "+f"(d[2]), "+f"(d[3])
        : "r"(a[0]), "r"(a[1]), "r"(a[2]), "r"(a[3]), "r"(b0), "r"(b1));
}

// fp16-accumulator variant: D/C are 2 regs (two half2: rows {g, g+8} x cols {2t,2t+1})
__device__ __forceinline__ void mma_f16h(uint32_t* d, const uint32_t* a,
                                         uint32_t b0, uint32_t b1) {
    asm volatile(
        "mma.sync.aligned.m16n8k16.row.col.f16.f16.f16.f16 "
        "{%0,%1}, {%2,%3,%4,%5}, {%6,%7}, {%0,%1};\n"
        : "+r"(d[0]), "+r"(d[1])
        : "r"(a[0]), "r"(a[1]), "r"(a[2]), "r"(a[3]), "r"(b0), "r"(b1));
}

__device__ __forceinline__ void ldsm_x4(uint32_t* r, uint32_t addr) {
    asm volatile("ldmatrix.sync.aligned.m8n8.x4.shared.b16 {%0,%1,%2,%3}, [%4];\n"
                 : "=r"(r[0]), "=r"(r[1]), "=r"(r[2]), "=r"(r[3]) : "r"(addr));
}

__device__ __forceinline__ uint32_t sm_u32(const void* p) {
    uint32_t a;
    asm("{ .reg .u64 t; cvta.to.shared.u64 t, %1; cvt.u32.u64 %0, t; }"
        : "=r"(a) : "l"(p));
    return a;
}

__device__ __forceinline__ void cp_async16(uint32_t dst, const void* src) {
    asm volatile("cp.async.cg.shared.global [%0], [%1], 16;\n"
                 :: "r"(dst), "l"(src) : "memory");
}

// ---------------------------------------------------------------------------
// Projection on fp16 tensor cores with register-prefetch pipeline (R10 proven).
// CTA = 128 thr (4 warps), 64 rows x 64 heads.
// ---------------------------------------------------------------------------
__global__ __launch_bounds__(128) void proj_kernel(
    const float* __restrict__ q, const float* __restrict__ k, const float* __restrict__ v,
    const float* __restrict__ Wq, const float* __restrict__ Wk, const float* __restrict__ Wv)
{
    __shared__ uint32_t sX[64 * LDW];
    __shared__ uint32_t sWm[64 * LDW];

    const int m = blockIdx.y;
    const float* __restrict__ x = (m == 0) ? q : (m == 1) ? k : v;
    const float* __restrict__ W = (m == 0) ? Wq : (m == 1) ? Wk : Wv;

    const int row0 = blockIdx.x * 64;
    const int tid  = threadIdx.x;
    const int w    = tid >> 5;
    const int lane = tid & 31;
    const int g    = lane >> 2;
    const int t    = lane & 3;

    const int rr = tid >> 4;
    const int fc = tid & 15;

    float o[8][4];
    #pragma unroll
    for (int j = 0; j < 8; j++)
        #pragma unroll
        for (int e = 0; e < 4; e++) o[j][e] = 0.0f;

    float4 rx[8], rw[8];
    #pragma unroll
    for (int it = 0; it < 8; it++) {
        int r = it * 8 + rr;
        rx[it] = *(const float4*)&x[(size_t)(row0 + r) * EMBD + fc * 4];
        rw[it] = *(const float4*)&W[(size_t)r * EMBD + fc * 4];
    }

    for (int kc0 = 0; kc0 < EMBD; kc0 += 64) {
        #pragma unroll
        for (int it = 0; it < 8; it++) {
            int r = it * 8 + rr;
            *(uint2*)&sX[r * LDW + fc * 2] =
                make_uint2(pack_h2(rx[it].x, rx[it].y), pack_h2(rx[it].z, rx[it].w));
            *(uint2*)&sWm[r * LDW + fc * 2] =
                make_uint2(pack_h2(rw[it].x, rw[it].y), pack_h2(rw[it].z, rw[it].w));
        }
        __syncthreads();

        if (kc0 + 64 < EMBD) {
            #pragma unroll
            for (int it = 0; it < 8; it++) {
                int r = it * 8 + rr;
                rx[it] = *(const float4*)&x[(size_t)(row0 + r) * EMBD + kc0 + 64 + fc * 4];
                rw[it] = *(const float4*)&W[(size_t)r * EMBD + kc0 + 64 + fc * 4];
            }
        }

        #pragma unroll
        for (int kc = 0; kc < 4; kc++) {
            uint32_t af[4];
            const uint32_t* xr = &sX[(16 * w + g) * LDW + 8 * kc + t];
            af[0] = xr[0];
            af[1] = xr[8 * LDW];
            af[2] = xr[4];
            af[3] = xr[8 * LDW + 4];
            #pragma unroll
            for (int j = 0; j < 8; j++) {
                mma_f16(o[j], af,
                        sWm[(8 * j + g) * LDW + 8 * kc + t],
                        sWm[(8 * j + g) * LDW + 8 * kc + t + 4]);
            }
        }
        __syncthreads();
    }

    const int rowg = row0 + 16 * w + g;
    if (m < 2) {
        const float sc = (m == 0) ? 0.125f * 1.4426950408889634f : 1.0f;
        __half* dst = (m == 0) ? g_Qh : g_Kh;
        #pragma unroll
        for (int j = 0; j < 8; j++) {
            int c = 8 * j + 2 * t;
            *(uint32_t*)&dst[(size_t)rowg * HD + c] = pack_h2(o[j][0] * sc, o[j][1] * sc);
            *(uint32_t*)&dst[(size_t)(rowg + 8) * HD + c] = pack_h2(o[j][2] * sc, o[j][3] * sc);
        }
    } else {
        const int b  = rowg >> 12;
        const int k2 = (rowg & (SS - 1)) >> 1;
        const uint32_t sel = (g & 1) ? 0x3276u : 0x5410u;
        #pragma unroll
        for (int j = 0; j < 8; j++) {
            int c = 8 * j + 2 * t;
            uint32_t w0 = pack_h2(o[j][0], o[j][1]);
            uint32_t w1 = pack_h2(o[j][2], o[j][3]);
            uint32_t p0 = __shfl_xor_sync(0xffffffffu, w0, 4);
            uint32_t p1 = __shfl_xor_sync(0xffffffffu, w1, 4);
            int d = c + (g & 1);
            size_t base = ((size_t)b * HD + d) * (SS / 2);
            g_Vp[base + k2]     = __byte_perm(w0, p0, sel);
            g_Vp[base + k2 + 4] = __byte_perm(w1, p1, sel);
        }
    }
}

// ---------------------------------------------------------------------------
// Flash attention v11: R10 structure (2-warp CTAs, warp = 32q x 64keys,
// register-resident P, split-K NSPLIT=3) with fp16-accum QK mma: the mma C
// fragment IS the exp2 input (no f32->f16 cvts in the softmax chain).
// grid (64, 4, 3) = 768 CTAs; smem K 2x2304 @0, V 2x2304 @4608 (36864 B).
// ---------------------------------------------------------------------------
#define SV_OFF 4608
#define SMEM_WORDS 9216

extern __shared__ uint32_t sm_dyn[];

__device__ __forceinline__ void issue_tile(uint32_t smem_base, int b, int kt, int buf, int tid)
{
    const __half*   Ksrc = g_Kh + ((size_t)b * SS + (size_t)kt * 64) * HD;
    const uint32_t* Vsrc = g_Vp + (size_t)b * HD * (SS / 2) + kt * 32;
    #pragma unroll
    for (int i = 0; i < 8; i++) {
        int ch = i * 64 + tid;              // 512 16B chunks per tile
        int r = ch >> 3, c = ch & 7;
        cp_async16(smem_base + (buf * 2304 + r * LDW + c * 4) * 4,
                   Ksrc + (size_t)r * HD + c * 8);
        cp_async16(smem_base + (SV_OFF + buf * 2304 + r * LDW + c * 4) * 4,
                   Vsrc + (size_t)r * (SS / 2) + c * 4);
    }
}

__global__ __launch_bounds__(64, 6) void attn_kernel()
{
    const int b    = blockIdx.y;
    const int z    = blockIdx.z;
    const int q0   = blockIdx.x * 64;
    const int tid  = threadIdx.x;
    const int w    = tid >> 5;      // warp: rows q0 + w*32 .. +31
    const int lane = tid & 31;
    const int g    = lane >> 2;
    const int t    = lane & 3;

    const uint32_t smem_base = sm_u32(sm_dyn);

    const int kt0 = (z == 0) ? 0 : (21 * z + 1);    // 0, 22, 43
    const int nkt = (z == 0) ? 22 : 21;

    issue_tile(smem_base, b, kt0, 0, tid);
    asm volatile("cp.async.commit_group;\n" ::: "memory");

    // Stage Q (64x64 fp16) into K-buf1 area (free until tile kt0+1 is issued)
    const __half* Qb = g_Qh + ((size_t)b * SS + q0) * HD;
    #pragma unroll
    for (int it = 0; it < 8; it++) {
        int idx = it * 64 + tid;
        int r = idx >> 3, c = idx & 7;
        *(uint4*)&sm_dyn[2304 + r * LDW + c * 4] = *(const uint4*)&Qb[(size_t)r * HD + c * 8];
    }
    __syncthreads();

    // Q fragments: 2 x 16-row tiles (live whole kernel)
    uint32_t qf[2][4][4];
    #pragma unroll
    for (int tt = 0; tt < 2; tt++) {
        const uint32_t* qp = &sm_dyn[2304 + (w * 32 + tt * 16 + g) * LDW];
        #pragma unroll
        for (int kc = 0; kc < 4; kc++) {
            qf[tt][kc][0] = qp[8 * kc + t];
            qf[tt][kc][1] = qp[8 * LDW + 8 * kc + t];
            qf[tt][kc][2] = qp[8 * kc + t + 4];
            qf[tt][kc][3] = qp[8 * LDW + 8 * kc + t + 4];
        }
    }

    float o[2][8][4];
    #pragma unroll
    for (int tt = 0; tt < 2; tt++)
        #pragma unroll
        for (int dj = 0; dj < 8; dj++)
            #pragma unroll
            for (int e = 0; e < 4; e++) o[tt][dj][e] = 0.0f;
    float l0[2] = {0.0f, 0.0f}, l1[2] = {0.0f, 0.0f};

    const uint32_t koff = ((lane & 7) * LDW + 4 * (lane >> 3)) * 4;
    const uint32_t voff = koff;

    int buf = 0;

    for (int it = 0; it < nkt; it++) {
        __syncthreads();   // both warps done with buf^1 (and qf extraction on it=0)
        if (it + 1 < nkt) {
            issue_tile(smem_base, b, kt0 + it + 1, buf ^ 1, tid);
            asm volatile("cp.async.commit_group;\n" ::: "memory");
            asm volatile("cp.async.wait_group 1;\n" ::: "memory");
        } else {
            asm volatile("cp.async.wait_group 0;\n" ::: "memory");
        }
        __syncthreads();

        const uint32_t kbase = smem_base + (buf * 2304) * 4 + koff;
        const uint32_t vbase = smem_base + (SV_OFF + buf * 2304) * 4 + voff;

        // ---- S = Q K^T (fp16 accum -> half2 C-frags feed exp2 directly) ----
        uint32_t pl[2][8], ph[2][8];
        __half2 la0[2] = {__float2half2_rn(0.0f), __float2half2_rn(0.0f)};
        __half2 la1[2] = {__float2half2_rn(0.0f), __float2half2_rn(0.0f)};

        #pragma unroll
        for (int j = 0; j < 8; j++) {
            uint32_t kf[8];
            ldsm_x4(kf,     kbase + j * (8 * LDW * 4));
            ldsm_x4(kf + 4, kbase + j * (8 * LDW * 4) + 64);
            #pragma unroll
            for (int tt = 0; tt < 2; tt++) {
                uint32_t sh[2] = {0u, 0u};
                mma_f16h(sh, qf[tt][0], kf[0], kf[1]);
                mma_f16h(sh, qf[tt][1], kf[2], kf[3]);
                mma_f16h(sh, qf[tt][2], kf[4], kf[5]);
                mma_f16h(sh, qf[tt][3], kf[6], kf[7]);
                __half2 e0 = h2exp2(*reinterpret_cast<__half2*>(&sh[0]));  // row w32+tt16+g
                __half2 e1 = h2exp2(*reinterpret_cast<__half2*>(&sh[1]));  // row +8
                la0[tt] = __hadd2(la0[tt], e0);
                la1[tt] = __hadd2(la1[tt], e1);
                pl[tt][j] = *reinterpret_cast<uint32_t*>(&e0);
                ph[tt][j] = *reinterpret_cast<uint32_t*>(&e1);
            }
        }
        #pragma unroll
        for (int tt = 0; tt < 2; tt++) {
            float2 f0 = __half22float2(la0[tt]); l0[tt] += f0.x + f0.y;
            float2 f1 = __half22float2(la1[tt]); l1[tt] += f1.x + f1.y;
        }

        // ---- O += P V : 64 keys = 4 A-chunks; V frags shared across tt ----
        #pragma unroll
        for (int dj = 0; dj < 8; dj++) {
            uint32_t vf[8];
            ldsm_x4(vf,     vbase + dj * (8 * LDW * 4));
            ldsm_x4(vf + 4, vbase + dj * (8 * LDW * 4) + 64);
            #pragma unroll
            for (int tt = 0; tt < 2; tt++) {
                uint32_t a0[4] = { pl[tt][0], ph[tt][0], pl[tt][1], ph[tt][1] };
                uint32_t a1[4] = { pl[tt][2], ph[tt][2], pl[tt][3], ph[tt][3] };
                uint32_t a2[4] = { pl[tt][4], ph[tt][4], pl[tt][5], ph[tt][5] };
                uint32_t a3[4] = { pl[tt][6], ph[tt][6], pl[tt][7], ph[tt][7] };
                mma_f16(o[tt][dj], a0, vf[0], vf[1]);
                mma_f16(o[tt][dj], a1, vf[2], vf[3]);
                mma_f16(o[tt][dj], a2, vf[4], vf[5]);
                mma_f16(o[tt][dj], a3, vf[6], vf[7]);
            }
        }
        buf ^= 1;
    }

    // ---- Reduce l over the 4 t-lanes; write unnormalized partials ----
    float* __restrict__ Ob = g_Op + (((size_t)z * BB + b) * SS + q0) * HD;
    float* __restrict__ Lb = g_Lp + ((size_t)z * BB + b) * SS + q0;
    #pragma unroll
    for (int tt = 0; tt < 2; tt++) {
        l0[tt] += __shfl_xor_sync(0xffffffffu, l0[tt], 1);
        l0[tt] += __shfl_xor_sync(0xffffffffu, l0[tt], 2);
        l1[tt] += __shfl_xor_sync(0xffffffffu, l1[tt], 1);
        l1[tt] += __shfl_xor_sync(0xffffffffu, l1[tt], 2);
        int r0 = w * 32 + tt * 16 + g;
        if (t == 0) {
            Lb[r0]     = l0[tt];
            Lb[r0 + 8] = l1[tt];
        }
        #pragma unroll
        for (int dj = 0; dj < 8; dj++) {
            int c = 8 * dj + 2 * t;
            *(float2*)&Ob[(size_t)r0 * HD + c] =
                make_float2(o[tt][dj][0], o[tt][dj][1]);
            *(float2*)&Ob[(size_t)(r0 + 8) * HD + c] =
                make_float2(o[tt][dj][2], o[tt][dj][3]);
        }
    }
}

// ---------------------------------------------------------------------------
// Merge: out = sum_z O_z / sum_z l_z.  4 float4 per thread (12 loads in flight).
// ---------------------------------------------------------------------------
__global__ __launch_bounds__(256) void merge_kernel(float* __restrict__ out)
{
    const int idx = blockIdx.x * 256 + threadIdx.x;      // 65536 threads
    const int row = idx >> 2;                             // 4 thread-groups per row
    float l = g_Lp[row] + g_Lp[BB * SS + row] + g_Lp[2 * BB * SS + row];
    float inv = 1.0f / l;
    const float4* O0 = (const float4*)g_Op;
    const float4* O1 = O0 + (size_t)BB * SS * HD / 4;
    const float4* O2 = O1 + (size_t)BB * SS * HD / 4;
    #pragma unroll
    for (int i = 0; i < 4; i++) {
        size_t e = (size_t)idx * 4 + i;
        float4 a = O0[e], c = O1[e], d = O2[e];
        ((float4*)out)[e] = make_float4((a.x + c.x + d.x) * inv, (a.y + c.y + d.y) * inv,
                                        (a.z + c.z + d.z) * inv, (a.w + c.w + d.w) * inv);
    }
}

// ---------------------------------------------------------------------------
extern "C" void kernel_launch(void* const* d_in, const int* in_sizes, int n_in,
                              void* d_out, int out_size)
{
    const float* q  = (const float*)d_in[0];
    const float* k  = (const float*)d_in[1];
    const float* v  = (const float*)d_in[2];
    const float* Wq = (const float*)d_in[3];
    const float* Wk = (const float*)d_in[4];
    const float* Wv = (const float*)d_in[5];
    float* out = (float*)d_out;

    const int smem_attn = SMEM_WORDS * (int)sizeof(uint32_t);   // 36864 B
    cudaFuncSetAttribute(attn_kernel, cudaFuncAttributeMaxDynamicSharedMemorySize, smem_attn);

    proj_kernel<<<dim3((BB * SS) / 64, 3), 128>>>(q, k, v, Wq, Wk, Wv);
    attn_kernel<<<dim3(SS / 64, BB, NSPLIT), 64, smem_attn>>>();
    merge_kernel<<<(BB * SS * HD / 16) / 256, 256>>>(out);
}